// round 15
// baseline (speedup 1.0000x reference)
#include <cuda_runtime.h>
#include <math.h>

// ------------------------------------------------------------------
// Static scratch (device globals: the sanctioned no-alloc workaround)
// ------------------------------------------------------------------
__device__ float g_ln[4096ull * 1024];          // layernorm output (tf32-rounded)
__device__ float g_q [4096ull * 1024];
__device__ float g_k [4096ull * 1024];
__device__ float g_v [4096ull * 1024];
__device__ float g_o [4096ull * 1024];          // attention output (pre-proj)
__device__ float g_h1[4096ull * 2048];          // FFN hidden
__device__ float g_sc[64ull * 1024 * 1024];     // scores [B*H, S, S] = 256 MB
__device__ float g_wt[50331648ull];             // tf32-rounded weights (192 MB)

// ------------------------------------------------------------------
// tf32 helpers
// ------------------------------------------------------------------
__device__ __forceinline__ unsigned f2tf(float f) {
    unsigned u;
    asm("cvt.rna.tf32.f32 %0, %1;" : "=r"(u) : "f"(f));
    return u;
}
__device__ __forceinline__ float rtf(float f) { return __uint_as_float(f2tf(f)); }

__device__ __forceinline__ void mma8(float* c, const unsigned* a, const unsigned* b) {
    asm volatile(
        "mma.sync.aligned.m16n8k8.row.col.f32.tf32.tf32.f32 "
        "{%0,%1,%2,%3}, {%4,%5,%6,%7}, {%8,%9}, {%0,%1,%2,%3};"
        : "+f"(c[0]), "+f"(c[1]), "+f"(c[2]), "+f"(c[3])
        : "r"(a[0]), "r"(a[1]), "r"(a[2]), "r"(a[3]), "r"(b[0]), "r"(b[1]));
}

// cp.async 16B gmem -> smem
__device__ __forceinline__ void cp16(unsigned* dst, const float* src) {
    unsigned d = (unsigned)__cvta_generic_to_shared(dst);
    asm volatile("cp.async.cg.shared.global [%0], [%1], 16;" :: "r"(d), "l"(src));
}
#define CP_COMMIT() asm volatile("cp.async.commit_group;")

// ------------------------------------------------------------------
// Weight tf32 pre-rounding (once per launch; elementwise)
// ------------------------------------------------------------------
__global__ void __launch_bounds__(256) conv_tf32(
    const float4* __restrict__ in, float4* __restrict__ out, int n4)
{
    int i = blockIdx.x * blockDim.x + threadIdx.x;
    if (i < n4) {
        float4 v = in[i];
        v.x = rtf(v.x); v.y = rtf(v.y); v.z = rtf(v.z); v.w = rtf(v.w);
        out[i] = v;
    }
}

// ------------------------------------------------------------------
// Block reductions (blockDim.x == 256)
// ------------------------------------------------------------------
__device__ __forceinline__ float block_sum(float v) {
    __shared__ float red[8];
    #pragma unroll
    for (int o = 16; o > 0; o >>= 1) v += __shfl_xor_sync(0xffffffffu, v, o);
    __syncthreads();
    if ((threadIdx.x & 31) == 0) red[threadIdx.x >> 5] = v;
    __syncthreads();
    float s = 0.f;
    #pragma unroll
    for (int i = 0; i < 8; i++) s += red[i];
    return s;
}
__device__ __forceinline__ float block_max(float v) {
    __shared__ float redm[8];
    #pragma unroll
    for (int o = 16; o > 0; o >>= 1) v = fmaxf(v, __shfl_xor_sync(0xffffffffu, v, o));
    __syncthreads();
    if ((threadIdx.x & 31) == 0) redm[threadIdx.x >> 5] = v;
    __syncthreads();
    float s = -3.4e38f;
    #pragma unroll
    for (int i = 0; i < 8; i++) s = fmaxf(s, redm[i]);
    return s;
}

// ------------------------------------------------------------------
// LayerNorm: 1 block per row, D=1024 (ddof=1 std, divide by std+eps)
// rnd!=0 -> round output to tf32 (it feeds a GEMM A-operand)
// ------------------------------------------------------------------
__global__ void __launch_bounds__(256) ln_kernel(
    const float* __restrict__ x, const float* __restrict__ g,
    const float* __restrict__ b, float* __restrict__ y, int rnd)
{
    const size_t row = blockIdx.x;
    const int t = threadIdx.x;
    float4 v = ((const float4*)(x + row * 1024))[t];
    float s = block_sum(v.x + v.y + v.z + v.w);
    float mean = s * (1.0f / 1024.0f);
    float d0 = v.x - mean, d1 = v.y - mean, d2 = v.z - mean, d3 = v.w - mean;
    float ss = block_sum(d0 * d0 + d1 * d1 + d2 * d2 + d3 * d3);
    float inv = 1.0f / (sqrtf(ss * (1.0f / 1023.0f)) + 1e-6f);
    float4 gg = ((const float4*)g)[t];
    float4 bb = ((const float4*)b)[t];
    float4 o;
    o.x = gg.x * d0 * inv + bb.x;
    o.y = gg.y * d1 * inv + bb.y;
    o.z = gg.z * d2 * inv + bb.z;
    o.w = gg.w * d3 * inv + bb.w;
    if (rnd) { o.x = rtf(o.x); o.y = rtf(o.y); o.z = rtf(o.z); o.w = rtf(o.w); }
    ((float4*)(y + row * 1024))[t] = o;
}

// ------------------------------------------------------------------
// Masked softmax; output rounded to tf32 (feeds PV A-operand)
// ------------------------------------------------------------------
__global__ void __launch_bounds__(256) softmax_kernel(
    float* __restrict__ S, const int* __restrict__ mask)
{
    const size_t row = blockIdx.x;
    const int t = threadIdx.x;
    const size_t q = row & 1023;
    const size_t b = row >> 14;   // 16 heads * 1024 q per batch
    float4 v = ((const float4*)(S + row * 1024))[t];
    int4 m = ((const int4*)(mask + (b * 1024 + q) * 1024))[t];
    if (m.x == 0) v.x = -1e9f;
    if (m.y == 0) v.y = -1e9f;
    if (m.z == 0) v.z = -1e9f;
    if (m.w == 0) v.w = -1e9f;
    float mx = block_max(fmaxf(fmaxf(v.x, v.y), fmaxf(v.z, v.w)));
    v.x = __expf(v.x - mx);
    v.y = __expf(v.y - mx);
    v.z = __expf(v.z - mx);
    v.w = __expf(v.w - mx);
    float s = block_sum(v.x + v.y + v.z + v.w);
    float inv = 1.0f / s;
    v.x = rtf(v.x * inv); v.y = rtf(v.y * inv);
    v.z = rtf(v.z * inv); v.w = rtf(v.w * inv);
    ((float4*)(S + row * 1024))[t] = v;
}

// ------------------------------------------------------------------
// Pipelined tf32 tensor-core GEMM (cp.async double-buffered).
// Inputs MUST be pre-rounded tf32-in-fp32 (no conversion in kernel).
//   C = alpha * A[M,K] @ B[N,K]^T (+bias, +relu, +residual, +round)
// 128 threads, warps 2x2 of 64x64, BM=BN=128, BK=32.
// smem pitch BK+4=36 -> conflict-free fragment loads (4g+t distinct mod 32).
// ------------------------------------------------------------------
template<int BM, int BN, int BK, int WM, int WN, int THREADS>
__device__ __forceinline__ void mma_pipe(
    const float* __restrict__ A, int lda,
    const float* __restrict__ B, int ldb,
    const float* __restrict__ bias,
    const float* __restrict__ R, int ldr,
    float* __restrict__ C, int ldc,
    int K, float alpha, int relu, int rnd)
{
    constexpr int MI = WM / 16;
    constexpr int NJ = WN / 8;
    constexpr int WX = BN / WN;
    constexpr int AP = BK + 4;
    constexpr int BP = BK + 4;
    constexpr int AW = BM * AP;                  // words per A stage
    constexpr int BW = BN * BP;
    constexpr int A4 = (BM * BK) / (4 * THREADS);
    constexpr int B4 = (BN * BK) / (4 * THREADS);
    constexpr int CH = BK / 4;                   // 16B chunks per row
    constexpr int RSTEP = THREADS / CH;          // rows advanced per unroll step
    static_assert((BM / WM) * (BN / WN) * 32 == THREADS, "warp layout");

    extern __shared__ unsigned sm[];

    const int tid  = threadIdx.x;
    const int warp = tid >> 5;
    const int lane = tid & 31;
    const int g = lane >> 2;
    const int t = lane & 3;
    const int wm0 = (warp / WX) * WM;
    const int wn0 = (warp % WX) * WN;
    const int m0 = blockIdx.y * BM;
    const int n0 = blockIdx.x * BN;

    // staging geometry: row = tid/CH (+RSTEP per step), chunk col = (tid%CH)*4
    const int r0 = tid / CH;
    const int c0 = (tid % CH) * 4;
    const float* Ag = A + (size_t)(m0 + r0) * lda + c0;
    const float* Bg = B + (size_t)(n0 + r0) * ldb + c0;
    unsigned* Asd = &sm[r0 * AP + c0];
    unsigned* Bsd = &sm[AW + r0 * BP + c0];

    const int nIter = K / BK;

    // stage 0
    #pragma unroll
    for (int u = 0; u < A4; u++) cp16(Asd + u * RSTEP * AP, Ag + (size_t)u * RSTEP * lda);
    #pragma unroll
    for (int u = 0; u < B4; u++) cp16(Bsd + u * RSTEP * BP, Bg + (size_t)u * RSTEP * ldb);
    CP_COMMIT();

    float acc[MI][NJ][4];
    #pragma unroll
    for (int i = 0; i < MI; i++)
        #pragma unroll
        for (int j = 0; j < NJ; j++) {
            acc[i][j][0] = 0.f; acc[i][j][1] = 0.f;
            acc[i][j][2] = 0.f; acc[i][j][3] = 0.f;
        }

    for (int it = 0; it < nIter; it++) {
        const int cur = (it & 1) * (AW + BW);
        if (it + 1 < nIter) {
            const int nxt = ((it + 1) & 1) * (AW + BW);
            const int kt = (it + 1) * BK;
            #pragma unroll
            for (int u = 0; u < A4; u++)
                cp16(Asd + nxt + u * RSTEP * AP, Ag + kt + (size_t)u * RSTEP * lda);
            #pragma unroll
            for (int u = 0; u < B4; u++)
                cp16(Bsd + nxt + u * RSTEP * BP, Bg + kt + (size_t)u * RSTEP * ldb);
            CP_COMMIT();
            asm volatile("cp.async.wait_group 1;");
        } else {
            asm volatile("cp.async.wait_group 0;");
        }
        __syncthreads();

        const unsigned* Asm = &sm[cur];
        const unsigned* Bsm = &sm[cur + AW];

        #pragma unroll
        for (int ks = 0; ks < BK / 8; ks++) {
            const int k0 = ks * 8;
            unsigned af[MI][4], bf[NJ][2];
            #pragma unroll
            for (int i = 0; i < MI; i++) {
                const int m = wm0 + i * 16 + g;
                af[i][0] = Asm[m * AP + k0 + t];
                af[i][1] = Asm[(m + 8) * AP + k0 + t];
                af[i][2] = Asm[m * AP + k0 + t + 4];
                af[i][3] = Asm[(m + 8) * AP + k0 + t + 4];
            }
            #pragma unroll
            for (int j = 0; j < NJ; j++) {
                const int n = wn0 + j * 8 + g;
                bf[j][0] = Bsm[n * BP + k0 + t];
                bf[j][1] = Bsm[n * BP + k0 + t + 4];
            }
            #pragma unroll
            for (int i = 0; i < MI; i++)
                #pragma unroll
                for (int j = 0; j < NJ; j++)
                    mma8(acc[i][j], af[i], bf[j]);
        }
        __syncthreads();
    }

    // epilogue: alpha, bias, relu, residual, optional tf32 rounding
    #pragma unroll
    for (int i = 0; i < MI; i++) {
        #pragma unroll
        for (int j = 0; j < NJ; j++) {
            const int m = m0 + wm0 + i * 16 + g;
            const int n = n0 + wn0 + j * 8 + 2 * t;
            float v0 = acc[i][j][0] * alpha;
            float v1 = acc[i][j][1] * alpha;
            float v2 = acc[i][j][2] * alpha;
            float v3 = acc[i][j][3] * alpha;
            if (bias) {
                float b0 = bias[n], b1 = bias[n + 1];
                v0 += b0; v1 += b1; v2 += b0; v3 += b1;
            }
            if (relu) {
                v0 = fmaxf(v0, 0.f); v1 = fmaxf(v1, 0.f);
                v2 = fmaxf(v2, 0.f); v3 = fmaxf(v3, 0.f);
            }
            if (R) {
                const float* r0p = R + (size_t)m * ldr + n;
                const float* r1p = R + (size_t)(m + 8) * ldr + n;
                v0 += r0p[0]; v1 += r0p[1];
                v2 += r1p[0]; v3 += r1p[1];
            }
            if (rnd) { v0 = rtf(v0); v1 = rtf(v1); v2 = rtf(v2); v3 = rtf(v3); }
            float2 s0; s0.x = v0; s0.y = v1;
            float2 s1; s1.x = v2; s1.y = v3;
            *(float2*)(C + (size_t)m * ldc + n) = s0;
            *(float2*)(C + (size_t)(m + 8) * ldc + n) = s1;
        }
    }
}

constexpr int PIPE_SMEM = 2 * (128 * 36 + 128 * 36) * 4;  // 73728 bytes

// Projections / FFN: C[M,N] = A[M,K] @ W[N,K]^T
__global__ void __launch_bounds__(128, 2) tg_pipe(
    const float* __restrict__ A, const float* __restrict__ W,
    const float* __restrict__ bias, const float* __restrict__ R,
    float* __restrict__ C, int N, int K, int relu, int rnd)
{
    mma_pipe<128, 128, 32, 64, 64, 128>(A, K, W, K, bias, R, N, C, N, K, 1.0f, relu, rnd);
}

// Batched QK^T: per z=(b*16+h): S[z] = 0.125 * Q_slice @ K_slice^T
__global__ void __launch_bounds__(128, 2) tqk_pipe(
    const float* __restrict__ Q, const float* __restrict__ Km,
    float* __restrict__ S)
{
    const int z = blockIdx.z, b = z >> 4, h = z & 15;
    const float* Aq = Q  + ((size_t)b << 20) + h * 64;
    const float* Bk = Km + ((size_t)b << 20) + h * 64;
    float* Cs = S + ((size_t)z << 20);
    mma_pipe<128, 128, 32, 64, 64, 128>(Aq, 1024, Bk, 1024,
                                        (const float*)0, (const float*)0, 0,
                                        Cs, 1024, 64, 0.125f, 0, 0);
}

// ------------------------------------------------------------------
// PV GEMM (old register-prefetch core; B is [K][N] row-major, N=64).
// Inputs pre-rounded; output rounded (feeds o-projection).
// ------------------------------------------------------------------
template<int BM, int BN, int BK, int WM, int WN, int THREADS>
__device__ __forceinline__ void mma_pv_core(
    const float* __restrict__ A, int lda,
    const float* __restrict__ B, int ldb,
    float* __restrict__ C, int ldc, int K)
{
    constexpr int MI = WM / 16;
    constexpr int NJ = WN / 8;
    constexpr int WX = BN / WN;
    constexpr int AP = BK + 4;
    constexpr int BP = BN + 8;
    constexpr int A4 = (BM * BK) / (4 * THREADS);
    constexpr int B4 = (BN * BK) / (4 * THREADS);

    __shared__ unsigned Asm[BM * AP];
    __shared__ unsigned Bsm[BK * BP];

    const int tid  = threadIdx.x;
    const int warp = tid >> 5;
    const int lane = tid & 31;
    const int g = lane >> 2;
    const int t = lane & 3;
    const int wm0 = (warp / WX) * WM;
    const int wn0 = (warp % WX) * WN;
    const int m0 = blockIdx.y * BM;
    const int n0 = blockIdx.x * BN;

    int am[A4], ak[A4];
    const float* Apt[A4];
    #pragma unroll
    for (int u = 0; u < A4; u++) {
        int idx = tid + THREADS * u;
        am[u] = idx / (BK / 4);
        ak[u] = (idx % (BK / 4)) * 4;
        Apt[u] = A + (size_t)(m0 + am[u]) * lda + ak[u];
    }
    int bm[B4], bk[B4];
    const float* Bpt[B4];
    #pragma unroll
    for (int u = 0; u < B4; u++) {
        int idx = tid + THREADS * u;
        bm[u] = idx / (BN / 4);
        bk[u] = (idx % (BN / 4)) * 4;
        Bpt[u] = B + (size_t)bm[u] * ldb + n0 + bk[u];
    }

    float4 pa[A4], pb[B4];
    #pragma unroll
    for (int u = 0; u < A4; u++) pa[u] = *(const float4*)Apt[u];
    #pragma unroll
    for (int u = 0; u < B4; u++) pb[u] = *(const float4*)Bpt[u];

    float acc[MI][NJ][4];
    #pragma unroll
    for (int i = 0; i < MI; i++)
        #pragma unroll
        for (int j = 0; j < NJ; j++) {
            acc[i][j][0] = 0.f; acc[i][j][1] = 0.f;
            acc[i][j][2] = 0.f; acc[i][j][3] = 0.f;
        }

    for (int kt = 0; kt < K; kt += BK) {
        #pragma unroll
        for (int u = 0; u < A4; u++)
            *(uint4*)&Asm[am[u] * AP + ak[u]] = *(const uint4*)&pa[u];
        #pragma unroll
        for (int u = 0; u < B4; u++)
            *(uint4*)&Bsm[bm[u] * BP + bk[u]] = *(const uint4*)&pb[u];
        __syncthreads();

        if (kt + BK < K) {
            #pragma unroll
            for (int u = 0; u < A4; u++)
                pa[u] = *(const float4*)(Apt[u] + (kt + BK));
            #pragma unroll
            for (int u = 0; u < B4; u++)
                pb[u] = *(const float4*)(Bpt[u] + (size_t)(kt + BK) * ldb);
        }

        #pragma unroll
        for (int ks = 0; ks < BK / 8; ks++) {
            const int k0 = ks * 8;
            unsigned af[MI][4], bf[NJ][2];
            #pragma unroll
            for (int i = 0; i < MI; i++) {
                const int m = wm0 + i * 16 + g;
                af[i][0] = Asm[m * AP + k0 + t];
                af[i][1] = Asm[(m + 8) * AP + k0 + t];
                af[i][2] = Asm[m * AP + k0 + t + 4];
                af[i][3] = Asm[(m + 8) * AP + k0 + t + 4];
            }
            #pragma unroll
            for (int j = 0; j < NJ; j++) {
                const int n = wn0 + j * 8 + g;
                bf[j][0] = Bsm[(k0 + t) * BP + n];
                bf[j][1] = Bsm[(k0 + t + 4) * BP + n];
            }
            #pragma unroll
            for (int i = 0; i < MI; i++)
                #pragma unroll
                for (int j = 0; j < NJ; j++)
                    mma8(acc[i][j], af[i], bf[j]);
        }
        __syncthreads();
    }

    #pragma unroll
    for (int i = 0; i < MI; i++) {
        #pragma unroll
        for (int j = 0; j < NJ; j++) {
            const int m = m0 + wm0 + i * 16 + g;
            const int n = n0 + wn0 + j * 8 + 2 * t;
            float2 s0, s1;
            s0.x = rtf(acc[i][j][0]); s0.y = rtf(acc[i][j][1]);
            s1.x = rtf(acc[i][j][2]); s1.y = rtf(acc[i][j][3]);
            *(float2*)(C + (size_t)m * ldc + n) = s0;
            *(float2*)(C + (size_t)(m + 8) * ldc + n) = s1;
        }
    }
}

__global__ void __launch_bounds__(256, 2) tpv(
    const float* __restrict__ P, const float* __restrict__ V,
    float* __restrict__ O)
{
    const int z = blockIdx.z, b = z >> 4, h = z & 15;
    const float* Ap = P + ((size_t)z << 20);
    const float* Bv = V + ((size_t)b << 20) + h * 64;
    float* Co = O + ((size_t)b << 20) + h * 64;
    mma_pv_core<128, 64, 16, 32, 32, 256>(Ap, 1024, Bv, 1024, Co, 1024, 1024);
}

// ------------------------------------------------------------------
// Host orchestration (graph-capturable: launches + one async D2D copy)
// ------------------------------------------------------------------
extern "C" void kernel_launch(void* const* d_in, const int* in_sizes, int n_in,
                              void* d_out, int out_size)
{
    (void)in_sizes; (void)n_in; (void)out_size;

    const float* we   = (const float*)d_in[0];
    const int*   mask = (const int*)d_in[1];
    const float* wq = (const float*)d_in[2],  *bq = (const float*)d_in[3];
    const float* wk = (const float*)d_in[4],  *bk = (const float*)d_in[5];
    const float* wv = (const float*)d_in[6],  *bv = (const float*)d_in[7];
    const float* wo = (const float*)d_in[8],  *bo = (const float*)d_in[9];
    const float* w1 = (const float*)d_in[10], *b1 = (const float*)d_in[11];
    const float* w2 = (const float*)d_in[12], *b2 = (const float*)d_in[13];
    const float* ln1a = (const float*)d_in[14], *ln1b = (const float*)d_in[15];
    const float* ln2a = (const float*)d_in[16], *ln2b = (const float*)d_in[17];
    const float* lnfa = (const float*)d_in[18], *lnfb = (const float*)d_in[19];

    float* x = (float*)d_out;   // residual stream lives in d_out

    float *ln, *q, *k, *v, *o, *h1, *sc, *wt;
    cudaGetSymbolAddress((void**)&ln, g_ln);
    cudaGetSymbolAddress((void**)&q,  g_q);
    cudaGetSymbolAddress((void**)&k,  g_k);
    cudaGetSymbolAddress((void**)&v,  g_v);
    cudaGetSymbolAddress((void**)&o,  g_o);
    cudaGetSymbolAddress((void**)&h1, g_h1);
    cudaGetSymbolAddress((void**)&sc, g_sc);
    cudaGetSymbolAddress((void**)&wt, g_wt);

    // tf32-rounded weight mirrors
    const size_t NQKV = 6ull * 1024 * 1024;   // 6 layers * d*d
    const size_t NFF  = 6ull * 2048 * 1024;   // 6 layers * f*d
    float* wq_t = wt;
    float* wk_t = wq_t + NQKV;
    float* wv_t = wk_t + NQKV;
    float* wo_t = wv_t + NQKV;
    float* w1_t = wo_t + NQKV;
    float* w2_t = w1_t + NFF;

    static bool attr_done = false;
    if (!attr_done) {
        cudaFuncSetAttribute(tg_pipe,  cudaFuncAttributeMaxDynamicSharedMemorySize, PIPE_SMEM);
        cudaFuncSetAttribute(tqk_pipe, cudaFuncAttributeMaxDynamicSharedMemorySize, PIPE_SMEM);
        attr_done = true;
    }

    cudaMemcpyAsync(x, we, sizeof(float) * 4096ull * 1024,
                    cudaMemcpyDeviceToDevice, 0);

    // pre-round all weights to tf32 (once per launch)
    conv_tf32<<<(int)(NQKV / 1024), 256>>>((const float4*)wq, (float4*)wq_t, (int)(NQKV / 4));
    conv_tf32<<<(int)(NQKV / 1024), 256>>>((const float4*)wk, (float4*)wk_t, (int)(NQKV / 4));
    conv_tf32<<<(int)(NQKV / 1024), 256>>>((const float4*)wv, (float4*)wv_t, (int)(NQKV / 4));
    conv_tf32<<<(int)(NQKV / 1024), 256>>>((const float4*)wo, (float4*)wo_t, (int)(NQKV / 4));
    conv_tf32<<<(int)(NFF  / 1024), 256>>>((const float4*)w1, (float4*)w1_t, (int)(NFF / 4));
    conv_tf32<<<(int)(NFF  / 1024), 256>>>((const float4*)w2, (float4*)w2_t, (int)(NFF / 4));

    const dim3 t128(128), t256(256);
    for (int L = 0; L < 6; ++L) {
        const size_t odd = (size_t)L * 1024 * 1024;   // d*d weights
        const size_t od  = (size_t)L * 1024;          // d vectors
        const size_t off = (size_t)L * 2048 * 1024;   // f*d weights
        const size_t of  = (size_t)L * 2048;          // f vectors

        // x -> ln1(x), tf32-rounded
        ln_kernel<<<4096, t256>>>(x, ln1a + od, ln1b + od, ln, 1);
        // Q/K/V projections (outputs rounded: feed attention GEMMs)
        tg_pipe<<<dim3(8, 32), t128, PIPE_SMEM>>>(ln, wq_t + odd, bq + od, (const float*)0, q, 1024, 1024, 0, 1);
        tg_pipe<<<dim3(8, 32), t128, PIPE_SMEM>>>(ln, wk_t + odd, bk + od, (const float*)0, k, 1024, 1024, 0, 1);
        tg_pipe<<<dim3(8, 32), t128, PIPE_SMEM>>>(ln, wv_t + odd, bv + od, (const float*)0, v, 1024, 1024, 0, 1);
        // attention
        tqk_pipe<<<dim3(8, 8, 64), t128, PIPE_SMEM>>>(q, k, sc);
        softmax_kernel<<<65536, t256>>>(sc, mask);
        tpv<<<dim3(1, 8, 64), t256>>>(sc, v, o);
        // output projection + residual (full fp32 output into x)
        tg_pipe<<<dim3(8, 32), t128, PIPE_SMEM>>>(o, wo_t + odd, bo + od, x, x, 1024, 1024, 0, 0);
        // FFN sublayer
        ln_kernel<<<4096, t256>>>(x, ln2a + od, ln2b + od, ln, 1);
        tg_pipe<<<dim3(16, 32), t128, PIPE_SMEM>>>(ln, w1_t + off, b1 + of, (const float*)0, h1, 2048, 1024, 1, 1);
        tg_pipe<<<dim3(8, 32), t128, PIPE_SMEM>>>(h1, w2_t + off, b2 + od, x, x, 1024, 2048, 0, 0);
    }
    // final layernorm (no rounding; output is the result)
    ln_kernel<<<4096, t256>>>(x, lnfa, lnfb, x, 0);
}

// round 16
// speedup vs baseline: 1.2007x; 1.2007x over previous
#include <cuda_runtime.h>
#include <math.h>

// ------------------------------------------------------------------
// Static scratch (device globals: the sanctioned no-alloc workaround)
// ------------------------------------------------------------------
__device__ float g_ln [4096ull * 1024];         // layernorm output (tf32-rounded)
__device__ float g_o  [4096ull * 1024];         // attention output (pre-proj)
__device__ float g_h1 [4096ull * 2048];         // FFN hidden
__device__ float g_qkv[4096ull * 3072];         // fused QKV output (48 MB)
__device__ float g_wt [50331648ull];            // tf32-rounded weights (192 MB)
__device__ float g_bqkv[6 * 3072];              // packed QKV biases
__device__ unsigned g_mb[4 * 1024 * 32];        // mask bitmask [b][q][32 words]

// ------------------------------------------------------------------
// tf32 helpers
// ------------------------------------------------------------------
__device__ __forceinline__ unsigned f2tf(float f) {
    unsigned u;
    asm("cvt.rna.tf32.f32 %0, %1;" : "=r"(u) : "f"(f));
    return u;
}
__device__ __forceinline__ float rtf(float f) { return __uint_as_float(f2tf(f)); }

__device__ __forceinline__ void mma8(float* c, const unsigned* a, const unsigned* b) {
    asm volatile(
        "mma.sync.aligned.m16n8k8.row.col.f32.tf32.tf32.f32 "
        "{%0,%1,%2,%3}, {%4,%5,%6,%7}, {%8,%9}, {%0,%1,%2,%3};"
        : "+f"(c[0]), "+f"(c[1]), "+f"(c[2]), "+f"(c[3])
        : "r"(a[0]), "r"(a[1]), "r"(a[2]), "r"(a[3]), "r"(b[0]), "r"(b[1]));
}

// cp.async 16B gmem -> smem
__device__ __forceinline__ void cp16(unsigned* dst, const float* src) {
    unsigned d = (unsigned)__cvta_generic_to_shared(dst);
    asm volatile("cp.async.cg.shared.global [%0], [%1], 16;" :: "r"(d), "l"(src));
}
#define CP_COMMIT() asm volatile("cp.async.commit_group;")
#define CP_WAIT0()  asm volatile("cp.async.wait_group 0;")
#define CP_WAIT1()  asm volatile("cp.async.wait_group 1;")

// ------------------------------------------------------------------
// Weight tf32 pre-rounding (once per launch)
// ------------------------------------------------------------------
__global__ void __launch_bounds__(256) conv_tf32(
    const float4* __restrict__ in, float4* __restrict__ out, int n4)
{
    int i = blockIdx.x * blockDim.x + threadIdx.x;
    if (i < n4) {
        float4 v = in[i];
        v.x = rtf(v.x); v.y = rtf(v.y); v.z = rtf(v.z); v.w = rtf(v.w);
        out[i] = v;
    }
}

// QKV repack: in = [6][1024][1024] (one of wq/wk/wv), out interleaved
// per layer: out[L*3M + sel*1M + e]
__global__ void __launch_bounds__(256) conv_tf32_qkv(
    const float4* __restrict__ in, float4* __restrict__ out, int sel)
{
    int i = blockIdx.x * blockDim.x + threadIdx.x;   // 6*262144
    if (i < 6 * 262144) {
        int L = i / 262144, e = i % 262144;
        float4 v = in[i];
        v.x = rtf(v.x); v.y = rtf(v.y); v.z = rtf(v.z); v.w = rtf(v.w);
        out[(size_t)L * (3 * 262144) + sel * 262144 + e] = v;
    }
}

// pack QKV biases: out[L][3072] = [bq[L]; bk[L]; bv[L]]
__global__ void __launch_bounds__(256) pack_bias(
    const float* __restrict__ bq, const float* __restrict__ bk,
    const float* __restrict__ bv, float* __restrict__ out)
{
    int i = blockIdx.x * blockDim.x + threadIdx.x;   // 18432
    if (i < 6 * 3072) {
        int L = i / 3072, r = i % 3072, sel = r >> 10, ii = r & 1023;
        const float* src = (sel == 0) ? bq : (sel == 1) ? bk : bv;
        out[i] = src[L * 1024 + ii];
    }
}

// mask -> bitmask: g_mb[(b*1024+q)*32 + w] bit i = (mask[b][q][w*32+i] != 0)
__global__ void __launch_bounds__(256) mask_bits_kernel(
    const int* __restrict__ mask, unsigned* __restrict__ mb)
{
    int w = blockIdx.x * blockDim.x + threadIdx.x;   // 4*1024*32 = 131072
    if (w < 131072) {
        int row = w >> 5, word = w & 31;
        const int* src = mask + (size_t)row * 1024 + word * 32;
        unsigned bits = 0;
        #pragma unroll
        for (int i = 0; i < 32; i++) bits |= (src[i] != 0 ? 1u : 0u) << i;
        mb[w] = bits;
    }
}

// ------------------------------------------------------------------
// Block reductions (blockDim.x == 256)
// ------------------------------------------------------------------
__device__ __forceinline__ float block_sum(float v) {
    __shared__ float red[8];
    #pragma unroll
    for (int o = 16; o > 0; o >>= 1) v += __shfl_xor_sync(0xffffffffu, v, o);
    __syncthreads();
    if ((threadIdx.x & 31) == 0) red[threadIdx.x >> 5] = v;
    __syncthreads();
    float s = 0.f;
    #pragma unroll
    for (int i = 0; i < 8; i++) s += red[i];
    return s;
}

// ------------------------------------------------------------------
// LayerNorm: 1 block per row, D=1024 (ddof=1 std, divide by std+eps)
// ------------------------------------------------------------------
__global__ void __launch_bounds__(256) ln_kernel(
    const float* __restrict__ x, const float* __restrict__ g,
    const float* __restrict__ b, float* __restrict__ y, int rnd)
{
    const size_t row = blockIdx.x;
    const int t = threadIdx.x;
    float4 v = ((const float4*)(x + row * 1024))[t];
    float s = block_sum(v.x + v.y + v.z + v.w);
    float mean = s * (1.0f / 1024.0f);
    float d0 = v.x - mean, d1 = v.y - mean, d2 = v.z - mean, d3 = v.w - mean;
    float ss = block_sum(d0 * d0 + d1 * d1 + d2 * d2 + d3 * d3);
    float inv = 1.0f / (sqrtf(ss * (1.0f / 1023.0f)) + 1e-6f);
    float4 gg = ((const float4*)g)[t];
    float4 bb = ((const float4*)b)[t];
    float4 o;
    o.x = gg.x * d0 * inv + bb.x;
    o.y = gg.y * d1 * inv + bb.y;
    o.z = gg.z * d2 * inv + bb.z;
    o.w = gg.w * d3 * inv + bb.w;
    if (rnd) { o.x = rtf(o.x); o.y = rtf(o.y); o.z = rtf(o.z); o.w = rtf(o.w); }
    ((float4*)(y + row * 1024))[t] = o;
}

// ------------------------------------------------------------------
// Pipelined tf32 tensor-core GEMM (cp.async double-buffered).
//   C = A[M,K] @ B[N,K]^T (+bias, +relu, +residual, +round)
// 128 threads, warps 2x2 of 64x64, BM=BN=128, BK=32.
// ------------------------------------------------------------------
template<int BM, int BN, int BK, int WM, int WN, int THREADS>
__device__ __forceinline__ void mma_pipe(
    const float* __restrict__ A, int lda,
    const float* __restrict__ B, int ldb,
    const float* __restrict__ bias,
    const float* __restrict__ R, int ldr,
    float* __restrict__ C, int ldc,
    int K, int relu, int rnd)
{
    constexpr int MI = WM / 16;
    constexpr int NJ = WN / 8;
    constexpr int WX = BN / WN;
    constexpr int AP = BK + 4;
    constexpr int BP = BK + 4;
    constexpr int AW = BM * AP;
    constexpr int BW = BN * BP;
    constexpr int A4 = (BM * BK) / (4 * THREADS);
    constexpr int B4 = (BN * BK) / (4 * THREADS);
    constexpr int CH = BK / 4;
    constexpr int RSTEP = THREADS / CH;
    static_assert((BM / WM) * (BN / WN) * 32 == THREADS, "warp layout");

    extern __shared__ unsigned sm[];

    const int tid  = threadIdx.x;
    const int warp = tid >> 5;
    const int lane = tid & 31;
    const int g = lane >> 2;
    const int t = lane & 3;
    const int wm0 = (warp / WX) * WM;
    const int wn0 = (warp % WX) * WN;
    const int m0 = blockIdx.y * BM;
    const int n0 = blockIdx.x * BN;

    const int r0 = tid / CH;
    const int c0 = (tid % CH) * 4;
    const float* Ag = A + (size_t)(m0 + r0) * lda + c0;
    const float* Bg = B + (size_t)(n0 + r0) * ldb + c0;
    unsigned* Asd = &sm[r0 * AP + c0];
    unsigned* Bsd = &sm[AW + r0 * BP + c0];

    const int nIter = K / BK;

    #pragma unroll
    for (int u = 0; u < A4; u++) cp16(Asd + u * RSTEP * AP, Ag + (size_t)u * RSTEP * lda);
    #pragma unroll
    for (int u = 0; u < B4; u++) cp16(Bsd + u * RSTEP * BP, Bg + (size_t)u * RSTEP * ldb);
    CP_COMMIT();

    float acc[MI][NJ][4];
    #pragma unroll
    for (int i = 0; i < MI; i++)
        #pragma unroll
        for (int j = 0; j < NJ; j++) {
            acc[i][j][0] = 0.f; acc[i][j][1] = 0.f;
            acc[i][j][2] = 0.f; acc[i][j][3] = 0.f;
        }

    for (int it = 0; it < nIter; it++) {
        const int cur = (it & 1) * (AW + BW);
        if (it + 1 < nIter) {
            const int nxt = ((it + 1) & 1) * (AW + BW);
            const int kt = (it + 1) * BK;
            #pragma unroll
            for (int u = 0; u < A4; u++)
                cp16(Asd + nxt + u * RSTEP * AP, Ag + kt + (size_t)u * RSTEP * lda);
            #pragma unroll
            for (int u = 0; u < B4; u++)
                cp16(Bsd + nxt + u * RSTEP * BP, Bg + kt + (size_t)u * RSTEP * ldb);
            CP_COMMIT();
            CP_WAIT1();
        } else {
            CP_WAIT0();
        }
        __syncthreads();

        const unsigned* Asm = &sm[cur];
        const unsigned* Bsm = &sm[cur + AW];

        #pragma unroll
        for (int ks = 0; ks < BK / 8; ks++) {
            const int k0 = ks * 8;
            unsigned af[MI][4], bf[NJ][2];
            #pragma unroll
            for (int i = 0; i < MI; i++) {
                const int m = wm0 + i * 16 + g;
                af[i][0] = Asm[m * AP + k0 + t];
                af[i][1] = Asm[(m + 8) * AP + k0 + t];
                af[i][2] = Asm[m * AP + k0 + t + 4];
                af[i][3] = Asm[(m + 8) * AP + k0 + t + 4];
            }
            #pragma unroll
            for (int j = 0; j < NJ; j++) {
                const int n = wn0 + j * 8 + g;
                bf[j][0] = Bsm[n * BP + k0 + t];
                bf[j][1] = Bsm[n * BP + k0 + t + 4];
            }
            #pragma unroll
            for (int i = 0; i < MI; i++)
                #pragma unroll
                for (int j = 0; j < NJ; j++)
                    mma8(acc[i][j], af[i], bf[j]);
        }
        __syncthreads();
    }

    #pragma unroll
    for (int i = 0; i < MI; i++) {
        #pragma unroll
        for (int j = 0; j < NJ; j++) {
            const int m = m0 + wm0 + i * 16 + g;
            const int n = n0 + wn0 + j * 8 + 2 * t;
            float v0 = acc[i][j][0];
            float v1 = acc[i][j][1];
            float v2 = acc[i][j][2];
            float v3 = acc[i][j][3];
            if (bias) {
                float b0 = bias[n], b1 = bias[n + 1];
                v0 += b0; v1 += b1; v2 += b0; v3 += b1;
            }
            if (relu) {
                v0 = fmaxf(v0, 0.f); v1 = fmaxf(v1, 0.f);
                v2 = fmaxf(v2, 0.f); v3 = fmaxf(v3, 0.f);
            }
            if (R) {
                const float* r0p = R + (size_t)m * ldr + n;
                const float* r1p = R + (size_t)(m + 8) * ldr + n;
                v0 += r0p[0]; v1 += r0p[1];
                v2 += r1p[0]; v3 += r1p[1];
            }
            if (rnd) { v0 = rtf(v0); v1 = rtf(v1); v2 = rtf(v2); v3 = rtf(v3); }
            float2 s0; s0.x = v0; s0.y = v1;
            float2 s1; s1.x = v2; s1.y = v3;
            *(float2*)(C + (size_t)m * ldc + n) = s0;
            *(float2*)(C + (size_t)(m + 8) * ldc + n) = s1;
        }
    }
}

constexpr int PIPE_SMEM = 2 * (128 * 36 + 128 * 36) * 4;  // 73728 bytes

__global__ void __launch_bounds__(128, 2) tg_pipe(
    const float* __restrict__ A, const float* __restrict__ W,
    const float* __restrict__ bias, const float* __restrict__ R,
    float* __restrict__ C, int N, int K, int relu, int rnd)
{
    mma_pipe<128, 128, 32, 64, 64, 128>(A, K, W, K, bias, R, N, C, N, K, relu, rnd);
}

// ------------------------------------------------------------------
// Flash attention: per block = one (b,h) and 128 q rows.
// QKV: [4096][3072] tf32-rounded; O: [4096][1024] rtf-rounded out.
// 256 threads = 8 warps, warp w owns q rows [16w,16w+16).
// 16 chunks of 64 keys; online softmax; P staged per-warp in smem.
// ------------------------------------------------------------------
constexpr int FLQ = 128 * 68;                // Qs words
constexpr int FLK = 64 * 68;                 // Ks words
constexpr int FLV = 64 * 72;                 // Vs words
constexpr int FLP = 8 * 16 * 68;             // Ps words (per-warp regions)
constexpr int FL_SMEM = (FLQ + FLK + FLV + FLP) * 4;   // 105472 bytes

__global__ void __launch_bounds__(256, 2) flash_kernel(
    const float* __restrict__ QKV, const unsigned* __restrict__ MB,
    float* __restrict__ O)
{
    extern __shared__ unsigned sm[];
    unsigned* Qs = sm;
    unsigned* Ks = Qs + FLQ;
    unsigned* Vs = Ks + FLK;
    unsigned* Ps = Vs + FLV;

    const int qt = blockIdx.x;         // 0..7
    const int z  = blockIdx.y;         // 0..63
    const int b  = z >> 4, h = z & 15;
    const int tid = threadIdx.x, warp = tid >> 5, lane = tid & 31;
    const int g = lane >> 2, t = lane & 3;

    const size_t base = ((size_t)b * 1024) * 3072 + (size_t)h * 64;
    const float* Qg = QKV + base + (size_t)(qt * 128) * 3072;
    const float* Kg = QKV + base + 1024;
    const float* Vg = QKV + base + 2048;

    // staging geometry: 16B chunks; 16 chunks per 64-float row
    const int ch4 = (tid & 15) * 4;
    const int rw  = tid >> 4;          // 0..15

    // load Q tile (128 rows)
    #pragma unroll
    for (int u = 0; u < 8; u++) {
        int row = rw + u * 16;
        cp16(Qs + row * 68 + ch4, Qg + (size_t)row * 3072 + ch4);
    }
    CP_COMMIT();

    // per-thread state: rows g (0) and g+8 (1) of warp's 16-row block
    float m0 = -1e30f, m1 = -1e30f, l0 = 0.f, l1 = 0.f;
    float o[8][4];
    #pragma unroll
    for (int j = 0; j < 8; j++) {
        o[j][0] = 0.f; o[j][1] = 0.f; o[j][2] = 0.f; o[j][3] = 0.f;
    }

    const int q0 = b * 1024 + qt * 128 + warp * 16 + g;  // MB row (row g)
    unsigned* Pw = Ps + warp * 16 * 68;
    const int mrow = warp * 16 + g;

    for (int c = 0; c < 16; c++) {
        // load K,V chunk (64 rows each)
        const float* Kc = Kg + (size_t)(c * 64) * 3072;
        const float* Vc = Vg + (size_t)(c * 64) * 3072;
        #pragma unroll
        for (int u = 0; u < 4; u++) {
            int row = rw + u * 16;
            cp16(Ks + row * 68 + ch4, Kc + (size_t)row * 3072 + ch4);
            cp16(Vs + row * 72 + ch4, Vc + (size_t)row * 3072 + ch4);
        }
        CP_COMMIT();
        CP_WAIT0();
        __syncthreads();

        // S = Q @ K^T  (K=64 -> 8 k-steps, N=64 -> 8 col-groups)
        float s[8][4];
        #pragma unroll
        for (int j = 0; j < 8; j++) {
            s[j][0] = 0.f; s[j][1] = 0.f; s[j][2] = 0.f; s[j][3] = 0.f;
        }
        #pragma unroll
        for (int ks = 0; ks < 8; ks++) {
            const int k0 = ks * 8;
            unsigned af[4];
            af[0] = Qs[mrow * 68 + k0 + t];
            af[1] = Qs[(mrow + 8) * 68 + k0 + t];
            af[2] = Qs[mrow * 68 + k0 + t + 4];
            af[3] = Qs[(mrow + 8) * 68 + k0 + t + 4];
            #pragma unroll
            for (int j = 0; j < 8; j++) {
                unsigned bf[2];
                bf[0] = Ks[(8 * j + g) * 68 + k0 + t];
                bf[1] = Ks[(8 * j + g) * 68 + k0 + t + 4];
                mma8(s[j], af, bf);
            }
        }

        // scale + mask + chunk row max
        const unsigned w00 = MB[q0 * 32 + 2 * c];
        const unsigned w01 = MB[q0 * 32 + 2 * c + 1];
        const unsigned w10 = MB[(q0 + 8) * 32 + 2 * c];
        const unsigned w11 = MB[(q0 + 8) * 32 + 2 * c + 1];
        float mx0 = -1e30f, mx1 = -1e30f;
        if ((w00 & w01 & w10 & w11) == 0xffffffffu) {
            #pragma unroll
            for (int j = 0; j < 8; j++) {
                #pragma unroll
                for (int e = 0; e < 2; e++) {
                    float v0 = s[j][e] * 0.125f;
                    float v1 = s[j][2 + e] * 0.125f;
                    s[j][e] = v0; s[j][2 + e] = v1;
                    mx0 = fmaxf(mx0, v0); mx1 = fmaxf(mx1, v1);
                }
            }
        } else {
            #pragma unroll
            for (int j = 0; j < 8; j++) {
                #pragma unroll
                for (int e = 0; e < 2; e++) {
                    const int cl = 8 * j + 2 * t + e;
                    const unsigned wd0 = (cl < 32) ? w00 : w01;
                    const unsigned wd1 = (cl < 32) ? w10 : w11;
                    float v0 = s[j][e] * 0.125f;
                    float v1 = s[j][2 + e] * 0.125f;
                    if (!((wd0 >> (cl & 31)) & 1u)) v0 = -1e9f;
                    if (!((wd1 >> (cl & 31)) & 1u)) v1 = -1e9f;
                    s[j][e] = v0; s[j][2 + e] = v1;
                    mx0 = fmaxf(mx0, v0); mx1 = fmaxf(mx1, v1);
                }
            }
        }
        mx0 = fmaxf(mx0, __shfl_xor_sync(0xffffffffu, mx0, 1));
        mx0 = fmaxf(mx0, __shfl_xor_sync(0xffffffffu, mx0, 2));
        mx1 = fmaxf(mx1, __shfl_xor_sync(0xffffffffu, mx1, 1));
        mx1 = fmaxf(mx1, __shfl_xor_sync(0xffffffffu, mx1, 2));

        const float nm0 = fmaxf(m0, mx0), nm1 = fmaxf(m1, mx1);
        const float f0 = __expf(m0 - nm0), f1 = __expf(m1 - nm1);
        m0 = nm0; m1 = nm1;

        // P = exp(s - m), round to tf32, stage; row sums
        float sum0 = 0.f, sum1 = 0.f;
        #pragma unroll
        for (int j = 0; j < 8; j++) {
            #pragma unroll
            for (int e = 0; e < 2; e++) {
                const int cl = 8 * j + 2 * t + e;
                float p0 = __expf(s[j][e] - nm0);
                float p1 = __expf(s[j][2 + e] - nm1);
                sum0 += p0; sum1 += p1;
                Pw[g * 68 + cl] = f2tf(p0);
                Pw[(g + 8) * 68 + cl] = f2tf(p1);
            }
        }
        sum0 += __shfl_xor_sync(0xffffffffu, sum0, 1);
        sum0 += __shfl_xor_sync(0xffffffffu, sum0, 2);
        sum1 += __shfl_xor_sync(0xffffffffu, sum1, 1);
        sum1 += __shfl_xor_sync(0xffffffffu, sum1, 2);
        l0 = l0 * f0 + sum0;
        l1 = l1 * f1 + sum1;

        // rescale O accumulators
        #pragma unroll
        for (int j = 0; j < 8; j++) {
            o[j][0] *= f0; o[j][1] *= f0;
            o[j][2] *= f1; o[j][3] *= f1;
        }
        __syncwarp();

        // O += P @ V  (K=64 keys -> 8 k-steps; N=64 d-cols -> 8 groups)
        #pragma unroll
        for (int kk = 0; kk < 8; kk++) {
            const int k0 = kk * 8;
            unsigned af[4];
            af[0] = Pw[g * 68 + k0 + t];
            af[1] = Pw[(g + 8) * 68 + k0 + t];
            af[2] = Pw[g * 68 + k0 + t + 4];
            af[3] = Pw[(g + 8) * 68 + k0 + t + 4];
            #pragma unroll
            for (int j = 0; j < 8; j++) {
                unsigned bf[2];
                bf[0] = Vs[(k0 + t) * 72 + 8 * j + g];
                bf[1] = Vs[(k0 + t + 4) * 72 + 8 * j + g];
                mma8(o[j], af, bf);
            }
        }
        __syncthreads();   // all warps done with Ks/Vs before next chunk load
    }

    // epilogue: normalize, round to tf32 (feeds O-projection GEMM)
    const float inv0 = 1.f / l0, inv1 = 1.f / l1;
    const int rg = b * 1024 + qt * 128 + warp * 16 + g;
    float* or0 = O + (size_t)rg * 1024 + h * 64;
    float* or1 = or0 + 8 * 1024;
    #pragma unroll
    for (int j = 0; j < 8; j++) {
        float2 s0, s1;
        s0.x = rtf(o[j][0] * inv0); s0.y = rtf(o[j][1] * inv0);
        s1.x = rtf(o[j][2] * inv1); s1.y = rtf(o[j][3] * inv1);
        *(float2*)(or0 + 8 * j + 2 * t) = s0;
        *(float2*)(or1 + 8 * j + 2 * t) = s1;
    }
}

// ------------------------------------------------------------------
// Host orchestration (graph-capturable: launches + one async D2D copy)
// ------------------------------------------------------------------
extern "C" void kernel_launch(void* const* d_in, const int* in_sizes, int n_in,
                              void* d_out, int out_size)
{
    (void)in_sizes; (void)n_in; (void)out_size;

    const float* we   = (const float*)d_in[0];
    const int*   mask = (const int*)d_in[1];
    const float* wq = (const float*)d_in[2],  *bq = (const float*)d_in[3];
    const float* wk = (const float*)d_in[4],  *bk = (const float*)d_in[5];
    const float* wv = (const float*)d_in[6],  *bv = (const float*)d_in[7];
    const float* wo = (const float*)d_in[8],  *bo = (const float*)d_in[9];
    const float* w1 = (const float*)d_in[10], *b1 = (const float*)d_in[11];
    const float* w2 = (const float*)d_in[12], *b2 = (const float*)d_in[13];
    const float* ln1a = (const float*)d_in[14], *ln1b = (const float*)d_in[15];
    const float* ln2a = (const float*)d_in[16], *ln2b = (const float*)d_in[17];
    const float* lnfa = (const float*)d_in[18], *lnfb = (const float*)d_in[19];

    float* x = (float*)d_out;   // residual stream lives in d_out

    float *ln, *o, *h1, *qkv, *wt, *bqkv;
    unsigned* mb;
    cudaGetSymbolAddress((void**)&ln,   g_ln);
    cudaGetSymbolAddress((void**)&o,    g_o);
    cudaGetSymbolAddress((void**)&h1,   g_h1);
    cudaGetSymbolAddress((void**)&qkv,  g_qkv);
    cudaGetSymbolAddress((void**)&wt,   g_wt);
    cudaGetSymbolAddress((void**)&bqkv, g_bqkv);
    cudaGetSymbolAddress((void**)&mb,   g_mb);

    // weight mirror layout: wqkv [6][3072][1024], then wo, w1, w2
    const size_t NQKV3 = 6ull * 3072 * 1024;   // 18,874,368
    const size_t NDD   = 6ull * 1024 * 1024;   // 6,291,456
    const size_t NFF   = 6ull * 2048 * 1024;   // 12,582,912
    float* wqkv_t = wt;
    float* wo_t = wqkv_t + NQKV3;
    float* w1_t = wo_t + NDD;
    float* w2_t = w1_t + NFF;

    static bool attr_done = false;
    if (!attr_done) {
        cudaFuncSetAttribute(tg_pipe, cudaFuncAttributeMaxDynamicSharedMemorySize, PIPE_SMEM);
        cudaFuncSetAttribute(flash_kernel, cudaFuncAttributeMaxDynamicSharedMemorySize, FL_SMEM);
        attr_done = true;
    }

    cudaMemcpyAsync(x, we, sizeof(float) * 4096ull * 1024,
                    cudaMemcpyDeviceToDevice, 0);

    // once-per-launch preprocessing
    conv_tf32_qkv<<<6144, 256>>>((const float4*)wq, (float4*)wqkv_t, 0);
    conv_tf32_qkv<<<6144, 256>>>((const float4*)wk, (float4*)wqkv_t, 1);
    conv_tf32_qkv<<<6144, 256>>>((const float4*)wv, (float4*)wqkv_t, 2);
    conv_tf32<<<(int)(NDD / 1024), 256>>>((const float4*)wo, (float4*)wo_t, (int)(NDD / 4));
    conv_tf32<<<(int)(NFF / 1024), 256>>>((const float4*)w1, (float4*)w1_t, (int)(NFF / 4));
    conv_tf32<<<(int)(NFF / 1024), 256>>>((const float4*)w2, (float4*)w2_t, (int)(NFF / 4));
    pack_bias<<<72, 256>>>(bq, bk, bv, bqkv);
    mask_bits_kernel<<<512, 256>>>(mask, mb);

    const dim3 t128(128), t256(256);
    for (int L = 0; L < 6; ++L) {
        const size_t odd = (size_t)L * 1024 * 1024;
        const size_t od  = (size_t)L * 1024;
        const size_t off = (size_t)L * 2048 * 1024;
        const size_t of  = (size_t)L * 2048;

        // attention sublayer
        ln_kernel<<<4096, t256>>>(x, ln1a + od, ln1b + od, ln, 1);
        tg_pipe<<<dim3(24, 32), t128, PIPE_SMEM>>>(
            ln, wqkv_t + (size_t)L * 3072 * 1024, bqkv + L * 3072,
            (const float*)0, qkv, 3072, 1024, 0, 1);
        flash_kernel<<<dim3(8, 64), t256, FL_SMEM>>>(qkv, mb, o);
        tg_pipe<<<dim3(8, 32), t128, PIPE_SMEM>>>(
            o, wo_t + odd, bo + od, x, x, 1024, 1024, 0, 0);
        // FFN sublayer
        ln_kernel<<<4096, t256>>>(x, ln2a + od, ln2b + od, ln, 1);
        tg_pipe<<<dim3(16, 32), t128, PIPE_SMEM>>>(
            ln, w1_t + off, b1 + of, (const float*)0, h1, 2048, 1024, 1, 1);
        tg_pipe<<<dim3(8, 32), t128, PIPE_SMEM>>>(
            h1, w2_t + off, b2 + od, x, x, 1024, 2048, 0, 0);
    }
    // final layernorm
    ln_kernel<<<4096, t256>>>(x, lnfa, lnfb, x, 0);
}